// round 9
// baseline (speedup 1.0000x reference)
#include <cuda_runtime.h>
#include <cuda_bf16.h>
#include <math.h>
#include <stdint.h>

#define BB   8
#define CC   64
#define HH   128
#define WW   128
#define HWSZ (HH*WW)          // 16384
#define NPIX (BB*HWSZ)        // 131072
#define NELEM (BB*CC*HWSZ)    // 8388608
#define EPS  1e-5f

// scratch: offsets(18) + mask(9) per pixel, layout [b][27][h][w]
__device__ float g_om[BB * 27 * HWSZ];
// [0..63] = sum(y) per channel, [64..127] = sum(y^2)
__device__ float g_sums[128];
// deform weights: per tap, B tile [64 outch x 64 ch] bf16, SW128, 8KB/tap
__device__ uint4 g_whi[9 * 512];
__device__ uint4 g_wlo[9 * 512];
// conv(offset+mask) weights: per tap, B tile [32 rows (27 used) x 64 ch], 4KB/tap
__device__ uint4 g_cwhi[9 * 256];
__device__ uint4 g_cwlo[9 * 256];

#define SMEM_SWZ128(o) ((o) ^ (((o) >> 3) & 0x70))

__device__ __forceinline__ uint32_t smem_u32(const void* p) {
    uint32_t a;
    asm("{ .reg .u64 t; cvta.to.shared.u64 t, %1; cvt.u32.u64 %0, t; }" : "=r"(a) : "l"(p));
    return a;
}
__device__ __forceinline__ void ldm_x4(uint32_t* r, uint32_t addr) {
    asm volatile("ldmatrix.sync.aligned.m8n8.x4.shared.b16 {%0,%1,%2,%3}, [%4];"
        : "=r"(r[0]), "=r"(r[1]), "=r"(r[2]), "=r"(r[3]) : "r"(addr));
}
__device__ __forceinline__ void mma16816(float* d, const uint32_t* a, const uint32_t* b) {
    asm volatile("mma.sync.aligned.m16n8k16.row.col.f32.bf16.bf16.f32 "
        "{%0,%1,%2,%3}, {%4,%5,%6,%7}, {%8,%9}, {%0,%1,%2,%3};"
        : "+f"(d[0]), "+f"(d[1]), "+f"(d[2]), "+f"(d[3])
        : "r"(a[0]), "r"(a[1]), "r"(a[2]), "r"(a[3]), "r"(b[0]), "r"(b[1]));
}
__device__ __forceinline__ void split_bf16(float a0, float a1, uint32_t& hi, uint32_t& lo) {
    asm("cvt.rn.satfinite.bf16x2.f32 %0, %1, %2;" : "=r"(hi) : "f"(a1), "f"(a0));
    float r0 = a0 - __uint_as_float(hi << 16);
    float r1 = a1 - __uint_as_float(hi & 0xffff0000u);
    asm("cvt.rn.satfinite.bf16x2.f32 %0, %1, %2;" : "=r"(lo) : "f"(r1), "f"(r0));
}

// ---------------------------------------------------------------------------
// Kernel 0: repack all weights into bf16 hi/lo pre-swizzled per-tap tiles.
// ---------------------------------------------------------------------------
__global__ __launch_bounds__(128) void repack_w_kernel(
    const float* __restrict__ w,
    const float* __restrict__ off_w, const float* __restrict__ mod_w)
{
    int id = blockIdx.x * 128 + threadIdx.x;
    if (blockIdx.x == 0 && threadIdx.x < 128) g_sums[threadIdx.x] = 0.f;

    if (id < 9 * 64 * 8) {
        int k  = id / 512;
        int r  = id % 512;
        int o  = r / 8;
        int cg = r % 8;
        uint32_t hp[4], lp[4];
#pragma unroll
        for (int jj = 0; jj < 4; ++jj) {
            int c0 = cg * 8 + 2 * jj;
            float a0 = w[o * 576 + (c0 + 0) * 9 + k];
            float a1 = w[o * 576 + (c0 + 1) * 9 + k];
            split_bf16(a0, a1, hp[jj], lp[jj]);
        }
        uint32_t off = SMEM_SWZ128((uint32_t)(o * 128 + cg * 16));
        g_whi[k * 512 + off / 16] = make_uint4(hp[0], hp[1], hp[2], hp[3]);
        g_wlo[k * 512 + off / 16] = make_uint4(lp[0], lp[1], lp[2], lp[3]);
    } else if (id < 9 * 64 * 8 + 9 * 32 * 8) {
        int id2 = id - 9 * 64 * 8;
        int k  = id2 / 256;
        int r  = id2 % 256;
        int j  = r / 8;
        int cg = r % 8;
        uint32_t hp[4], lp[4];
#pragma unroll
        for (int jj = 0; jj < 4; ++jj) {
            int c0 = cg * 8 + 2 * jj;
            float a0 = 0.f, a1 = 0.f;
            if (j < 18) {
                a0 = off_w[(j * 64 + c0 + 0) * 9 + k];
                a1 = off_w[(j * 64 + c0 + 1) * 9 + k];
            } else if (j < 27) {
                a0 = mod_w[((j - 18) * 64 + c0 + 0) * 9 + k];
                a1 = mod_w[((j - 18) * 64 + c0 + 1) * 9 + k];
            }
            split_bf16(a0, a1, hp[jj], lp[jj]);
        }
        uint32_t off = SMEM_SWZ128((uint32_t)(j * 128 + cg * 16));
        g_cwhi[k * 256 + off / 16] = make_uint4(hp[0], hp[1], hp[2], hp[3]);
        g_cwlo[k * 256 + off / 16] = make_uint4(lp[0], lp[1], lp[2], lp[3]);
    }
}

// ---------------------------------------------------------------------------
// Kernel 1: offset/mask 3x3 conv via split-bf16 mma.sync (as round 7).
// ---------------------------------------------------------------------------
__global__ __launch_bounds__(128) void conv_om_mma_kernel(
    const float* __restrict__ x,
    const float* __restrict__ off_b, const float* __restrict__ mod_b)
{
    extern __shared__ __align__(16) char dynsm[];
    uint32_t dynb = smem_u32(dynsm);
    uint32_t ab   = (dynb + 1023) & ~1023u;
    char* aptr    = dynsm + (ab - dynb);
    uint32_t sm_ahi = ab;
    uint32_t sm_alo = ab + 16384;
    uint32_t sm_bhi = ab + 32768;
    uint32_t sm_blo = ab + 36864;

    int tid  = threadIdx.x;
    int wid  = tid >> 5;
    int lane = tid & 31;

    int gid = blockIdx.x * 128 + tid;
    int b   = gid >> 14;
    int hw  = gid & (HWSZ - 1);
    int h   = hw >> 7;
    int wc  = hw & (WW - 1);
    const float* xb = x + b * CC * HWSZ;

    float acc[2][4][4];
#pragma unroll
    for (int m = 0; m < 2; ++m)
#pragma unroll
        for (int n = 0; n < 4; ++n)
#pragma unroll
            for (int q = 0; q < 4; ++q) acc[m][n][q] = 0.f;

    for (int k = 0; k < 9; ++k) {
        {
            const uint4* sh = g_cwhi + k * 256;
            const uint4* sl = g_cwlo + k * 256;
            uint4* dh = (uint4*)(aptr + 32768);
            uint4* dl = (uint4*)(aptr + 36864);
            dh[tid] = sh[tid];             dl[tid] = sl[tid];
            dh[tid + 128] = sh[tid + 128]; dl[tid + 128] = sl[tid + 128];
        }

        int y  = h + k / 3 - 1;
        int xx = wc + k % 3 - 1;
        bool ok = (y >= 0) && (y < HH) && (xx >= 0) && (xx < WW);
        const float* xp = xb + y * WW + xx;
        uint32_t rowoff = (uint32_t)(tid * 128);
#pragma unroll
        for (int g8 = 0; g8 < 8; ++g8) {
            uint32_t hp[4], lp[4];
#pragma unroll
            for (int jj = 0; jj < 4; ++jj) {
                int c0 = g8 * 8 + 2 * jj;
                float a0 = ok ? xp[(c0 + 0) * HWSZ] : 0.f;
                float a1 = ok ? xp[(c0 + 1) * HWSZ] : 0.f;
                split_bf16(a0, a1, hp[jj], lp[jj]);
            }
            uint32_t off = SMEM_SWZ128(rowoff + (uint32_t)(g8 * 16));
            *(uint4*)(aptr + off)         = make_uint4(hp[0], hp[1], hp[2], hp[3]);
            *(uint4*)(aptr + 16384 + off) = make_uint4(lp[0], lp[1], lp[2], lp[3]);
        }
        __syncthreads();

        int m0 = wid * 32;
        int brow = (lane & 7) + ((lane >> 4) << 3);
        int bcolh = ((lane >> 3) & 1) * 16;
        int arow = (lane & 15);
        int acolh = ((lane >> 4) & 1) * 16;
#pragma unroll
        for (int s = 0; s < 4; ++s) {
            uint32_t bh[4][2], bl[4][2];
#pragma unroll
            for (int np = 0; np < 2; ++np) {
                uint32_t off = SMEM_SWZ128((uint32_t)((np * 16 + brow) * 128 + s * 32 + bcolh));
                uint32_t r[4];
                ldm_x4(r, sm_bhi + off);
                bh[np*2][0] = r[0]; bh[np*2][1] = r[1];
                bh[np*2+1][0] = r[2]; bh[np*2+1][1] = r[3];
                ldm_x4(r, sm_blo + off);
                bl[np*2][0] = r[0]; bl[np*2][1] = r[1];
                bl[np*2+1][0] = r[2]; bl[np*2+1][1] = r[3];
            }
#pragma unroll
            for (int mt = 0; mt < 2; ++mt) {
                uint32_t off = SMEM_SWZ128((uint32_t)((m0 + mt * 16 + arow) * 128 + s * 32 + acolh));
                uint32_t ah[4], al[4];
                ldm_x4(ah, sm_ahi + off);
                ldm_x4(al, sm_alo + off);
#pragma unroll
                for (int n = 0; n < 4; ++n) {
                    mma16816(acc[mt][n], ah, bh[n]);
                    mma16816(acc[mt][n], ah, bl[n]);
                    mma16816(acc[mt][n], al, bh[n]);
                }
            }
        }
        __syncthreads();
    }

    {
        int m0 = wid * 32;
        int g  = lane >> 2;
        int t  = lane & 3;
#pragma unroll
        for (int mt = 0; mt < 2; ++mt) {
#pragma unroll
            for (int n = 0; n < 4; ++n) {
                int c0 = n * 8 + t * 2;
                int gq = c0 >> 2;
                int sub = (c0 & 3) * 4;
                int r0 = m0 + mt * 16 + g;
                int r1 = r0 + 8;
                uint32_t o0 = (uint32_t)(r0 * 128 + (((gq + r0) & 7) * 16) + sub);
                uint32_t o1 = (uint32_t)(r1 * 128 + (((gq + r1) & 7) * 16) + sub);
                *(float2*)(aptr + o0) = make_float2(acc[mt][n][0], acc[mt][n][1]);
                *(float2*)(aptr + o1) = make_float2(acc[mt][n][2], acc[mt][n][3]);
            }
        }
    }
    __syncthreads();

    float v[32];
#pragma unroll
    for (int g = 0; g < 8; ++g) {
        float4 q = *(float4*)(aptr + tid * 128 + (((g + tid) & 7) * 16));
        v[g * 4 + 0] = q.x; v[g * 4 + 1] = q.y;
        v[g * 4 + 2] = q.z; v[g * 4 + 3] = q.w;
    }
    float* om = g_om + b * 27 * HWSZ + hw;
#pragma unroll
    for (int j = 0; j < 18; ++j) om[j * HWSZ] = v[j] + __ldg(&off_b[j]);
#pragma unroll
    for (int j = 18; j < 27; ++j) {
        float a = v[j] + __ldg(&mod_b[j - 18]);
        om[j * HWSZ] = 2.f / (1.f + expf(-a));
    }
}

// ---------------------------------------------------------------------------
// bilinear setup + one 8-channel gather chunk (deform helpers)
// ---------------------------------------------------------------------------
__device__ __forceinline__ void bilin_setup(
    const float* om, int k, int h, int wc,
    float& w00, float& w01, float& w10, float& w11,
    int& i00, int& i01, int& i10, int& i11)
{
    float dy = om[(2 * k + 0) * HWSZ];
    float dx = om[(2 * k + 1) * HWSZ];
    float m  = om[(18 + k) * HWSZ];

    float py = (float)(h + k / 3 - 1) + dy;
    float px = (float)(wc + k % 3 - 1) + dx;
    float y0f = floorf(py), x0f = floorf(px);
    float ly = py - y0f, lx = px - x0f;
    int y0 = (int)y0f, x0 = (int)x0f;
    int y1 = y0 + 1, x1 = x0 + 1;

    bool vy0 = (y0 >= 0) && (y0 < HH);
    bool vy1 = (y1 >= 0) && (y1 < HH);
    bool vx0 = (x0 >= 0) && (x0 < WW);
    bool vx1 = (x1 >= 0) && (x1 < WW);
    int cy0 = min(max(y0, 0), HH - 1), cy1 = min(max(y1, 0), HH - 1);
    int cx0 = min(max(x0, 0), WW - 1), cx1 = min(max(x1, 0), WW - 1);
    i00 = cy0 * WW + cx0; i01 = cy0 * WW + cx1;
    i10 = cy1 * WW + cx0; i11 = cy1 * WW + cx1;

    w00 = (vy0 && vx0) ? (1.f - ly) * (1.f - lx) * m : 0.f;
    w01 = (vy0 && vx1) ? (1.f - ly) * lx * m : 0.f;
    w10 = (vy1 && vx0) ? ly * (1.f - lx) * m : 0.f;
    w11 = (vy1 && vx1) ? ly * lx * m : 0.f;
}

__device__ __forceinline__ void gather_chunk(
    const float* xb, int g8,
    float w00, float w01, float w10, float w11,
    int i00, int i01, int i10, int i11,
    char* abuf, uint32_t rowoff)
{
    float v[8];
#pragma unroll
    for (int j = 0; j < 8; ++j) {
        const float* xc = xb + (g8 * 8 + j) * HWSZ;
        v[j] = w00 * xc[i00] + w01 * xc[i01] + w10 * xc[i10] + w11 * xc[i11];
    }
    uint32_t hp[4], lp[4];
#pragma unroll
    for (int jj = 0; jj < 4; ++jj)
        split_bf16(v[2 * jj], v[2 * jj + 1], hp[jj], lp[jj]);
    uint32_t off = SMEM_SWZ128(rowoff + (uint32_t)(g8 * 16));
    *(uint4*)(abuf + off)         = make_uint4(hp[0], hp[1], hp[2], hp[3]);
    *(uint4*)(abuf + 16384 + off) = make_uint4(lp[0], lp[1], lp[2], lp[3]);
}

// ---------------------------------------------------------------------------
// Kernel 2: PIPELINED deformable gather -> split-bf16 mma.sync GEMM.
// Double-buffered A (32KB x2) + B (16KB x2); one __syncthreads per tap.
// Gather for tap k+1 is interleaved with the mma s-steps of tap k so the
// gather LDG latency hides under tensor work.
// ---------------------------------------------------------------------------
__global__ __launch_bounds__(128) void deform_mma_kernel(
    const float* __restrict__ x,
    const float* __restrict__ bias,
    float* __restrict__ out)
{
    extern __shared__ __align__(16) char dynsm[];
    uint32_t dynb = smem_u32(dynsm);
    uint32_t ab   = (dynb + 1023) & ~1023u;
    char* aptr    = dynsm + (ab - dynb);
    // layout: A bufs at ab + p*32768 (hi @0, lo @16384); B bufs at ab+65536+p*16384

    __shared__ float ssum[64];
    __shared__ float ssq[64];

    int tid  = threadIdx.x;
    int wid  = tid >> 5;
    int lane = tid & 31;

    if (tid < 64) { ssum[tid] = 0.f; ssq[tid] = 0.f; }

    int gid = blockIdx.x * 128 + tid;
    int b   = gid >> 14;
    int hw  = gid & (HWSZ - 1);
    int h   = hw >> 7;
    int wc  = hw & (WW - 1);
    const float* xb = x + b * CC * HWSZ;
    const float* om = g_om + b * 27 * HWSZ + hw;
    uint32_t rowoff = (uint32_t)(tid * 128);

    float acc[2][8][4];
#pragma unroll
    for (int m = 0; m < 2; ++m)
#pragma unroll
        for (int n = 0; n < 8; ++n)
#pragma unroll
            for (int q = 0; q < 4; ++q) acc[m][n][q] = 0.f;

    // ---- prologue: stage B0 + A0 ----
    {
        const uint4* sh = g_whi;
        const uint4* sl = g_wlo;
        uint4* dh = (uint4*)(aptr + 65536);
        uint4* dl = (uint4*)(aptr + 65536 + 8192);
#pragma unroll
        for (int i = 0; i < 4; ++i) {
            dh[tid + 128 * i] = sh[tid + 128 * i];
            dl[tid + 128 * i] = sl[tid + 128 * i];
        }
        float w00, w01, w10, w11; int i00, i01, i10, i11;
        bilin_setup(om, 0, h, wc, w00, w01, w10, w11, i00, i01, i10, i11);
#pragma unroll
        for (int g8 = 0; g8 < 8; ++g8)
            gather_chunk(xb, g8, w00, w01, w10, w11, i00, i01, i10, i11, aptr, rowoff);
    }
    __syncthreads();

    int m0 = wid * 32;
    int brow = (lane & 7) + ((lane >> 4) << 3);
    int bcolh = ((lane >> 3) & 1) * 16;
    int arow = (lane & 15);
    int acolh = ((lane >> 4) & 1) * 16;

    for (int k = 0; k < 9; ++k) {
        int cur = k & 1;
        int nxt = cur ^ 1;
        bool more = (k < 8);
        uint32_t sm_ahi = ab + cur * 32768;
        uint32_t sm_alo = sm_ahi + 16384;
        uint32_t sm_bhi = ab + 65536 + cur * 16384;
        uint32_t sm_blo = sm_bhi + 8192;
        char* an = aptr + nxt * 32768;
        char* bn = aptr + 65536 + nxt * 16384;

        // stage next B (independent of current mma)
        if (more) {
            const uint4* sh = g_whi + (k + 1) * 512;
            const uint4* sl = g_wlo + (k + 1) * 512;
            uint4* dh = (uint4*)bn;
            uint4* dl = (uint4*)(bn + 8192);
#pragma unroll
            for (int i = 0; i < 4; ++i) {
                dh[tid + 128 * i] = sh[tid + 128 * i];
                dl[tid + 128 * i] = sl[tid + 128 * i];
            }
        }
        float w00 = 0.f, w01 = 0.f, w10 = 0.f, w11 = 0.f;
        int i00 = 0, i01 = 0, i10 = 0, i11 = 0;
        if (more)
            bilin_setup(om, k + 1, h, wc, w00, w01, w10, w11, i00, i01, i10, i11);

        // interleave: 2 gather chunks (next tap) per mma s-step (current tap)
#pragma unroll
        for (int s = 0; s < 4; ++s) {
            if (more) {
                gather_chunk(xb, 2 * s + 0, w00, w01, w10, w11, i00, i01, i10, i11, an, rowoff);
                gather_chunk(xb, 2 * s + 1, w00, w01, w10, w11, i00, i01, i10, i11, an, rowoff);
            }
            uint32_t bh[8][2], bl[8][2];
#pragma unroll
            for (int np = 0; np < 4; ++np) {
                uint32_t off = SMEM_SWZ128((uint32_t)((np * 16 + brow) * 128 + s * 32 + bcolh));
                uint32_t r[4];
                ldm_x4(r, sm_bhi + off);
                bh[np*2][0] = r[0]; bh[np*2][1] = r[1];
                bh[np*2+1][0] = r[2]; bh[np*2+1][1] = r[3];
                ldm_x4(r, sm_blo + off);
                bl[np*2][0] = r[0]; bl[np*2][1] = r[1];
                bl[np*2+1][0] = r[2]; bl[np*2+1][1] = r[3];
            }
#pragma unroll
            for (int mt = 0; mt < 2; ++mt) {
                uint32_t off = SMEM_SWZ128((uint32_t)((m0 + mt * 16 + arow) * 128 + s * 32 + acolh));
                uint32_t ah[4], al[4];
                ldm_x4(ah, sm_ahi + off);
                ldm_x4(al, sm_alo + off);
#pragma unroll
                for (int n = 0; n < 8; ++n) {
                    mma16816(acc[mt][n], ah, bh[n]);
                    mma16816(acc[mt][n], ah, bl[n]);
                    mma16816(acc[mt][n], al, bh[n]);
                }
            }
        }
        __syncthreads();
    }

    // ---- write fragments to smem D[128][64] fp32 (XOR-swizzled 256B rows) ----
    {
        int g  = lane >> 2;
        int t  = lane & 3;
#pragma unroll
        for (int mt = 0; mt < 2; ++mt) {
#pragma unroll
            for (int n = 0; n < 8; ++n) {
                int col16 = n * 2 + (t >> 1);
                int lowb  = (t & 1) * 8;
                int r0 = m0 + mt * 16 + g;
                int r1 = r0 + 8;
                uint32_t o0 = (uint32_t)(r0 * 256 + (((col16 + r0) & 15) * 16) + lowb);
                uint32_t o1 = (uint32_t)(r1 * 256 + (((col16 + r1) & 15) * 16) + lowb);
                *(float2*)(aptr + o0) = make_float2(acc[mt][n][0], acc[mt][n][1]);
                *(float2*)(aptr + o1) = make_float2(acc[mt][n][2], acc[mt][n][3]);
            }
        }
    }
    __syncthreads();

    float v[64];
#pragma unroll
    for (int j = 0; j < 16; ++j) {
        float4 q = *(float4*)(aptr + tid * 256 + (((j + tid) & 15) * 16));
        v[j * 4 + 0] = q.x; v[j * 4 + 1] = q.y;
        v[j * 4 + 2] = q.z; v[j * 4 + 3] = q.w;
    }

    float* yp = out + b * CC * HWSZ + hw;
#pragma unroll
    for (int o = 0; o < 64; ++o) {
        float val = v[o] + __ldg(&bias[o]);
        yp[o * HWSZ] = val;
        float s = val, q = val * val;
#pragma unroll
        for (int d = 16; d > 0; d >>= 1) {
            s += __shfl_down_sync(0xffffffffu, s, d);
            q += __shfl_down_sync(0xffffffffu, q, d);
        }
        if (lane == 0) { atomicAdd(&ssum[o], s); atomicAdd(&ssq[o], q); }
    }
    __syncthreads();
    if (tid < 64) {
        atomicAdd(&g_sums[tid], ssum[tid]);
        atomicAdd(&g_sums[64 + tid], ssq[tid]);
    }
}

// ---------------------------------------------------------------------------
// Kernel 3: batchnorm + gamma/beta + relu, float4-vectorized, in place.
// ---------------------------------------------------------------------------
__global__ __launch_bounds__(256) void bn_relu_kernel(
    float4* __restrict__ out,
    const float* __restrict__ gamma, const float* __restrict__ beta)
{
    int gid = blockIdx.x * 256 + threadIdx.x;
    int c = (gid >> 12) & 63;
    const float N = (float)NPIX;
    float s = g_sums[c], q = g_sums[64 + c];
    float mean = s / N;
    float var = q / N - mean * mean;
    float inv = rsqrtf(var + EPS);
    float scale = __ldg(&gamma[c]) * inv;
    float shift = __ldg(&beta[c]) - mean * scale;
    float4 v = out[gid];
    v.x = fmaxf(v.x * scale + shift, 0.f);
    v.y = fmaxf(v.y * scale + shift, 0.f);
    v.z = fmaxf(v.z * scale + shift, 0.f);
    v.w = fmaxf(v.w * scale + shift, 0.f);
    out[gid] = v;
}

// ---------------------------------------------------------------------------
extern "C" void kernel_launch(void* const* d_in, const int* in_sizes, int n_in,
                              void* d_out, int out_size)
{
    const float* x     = (const float*)d_in[0];
    const float* off_w = (const float*)d_in[1];
    const float* off_b = (const float*)d_in[2];
    const float* mod_w = (const float*)d_in[3];
    const float* mod_b = (const float*)d_in[4];
    const float* w     = (const float*)d_in[5];
    const float* bias  = (const float*)d_in[6];
    const float* gamma = (const float*)d_in[7];
    const float* beta  = (const float*)d_in[8];
    float* out = (float*)d_out;

    static bool attr_set = false;
    if (!attr_set) {
        cudaFuncSetAttribute(deform_mma_kernel,
                             cudaFuncAttributeMaxDynamicSharedMemorySize, 99328);
        cudaFuncSetAttribute(conv_om_mma_kernel,
                             cudaFuncAttributeMaxDynamicSharedMemorySize, 41984);
        attr_set = true;
    }

    repack_w_kernel<<<54, 128>>>(w, off_w, mod_w);
    conv_om_mma_kernel<<<NPIX / 128, 128, 41984>>>(x, off_b, mod_b);
    deform_mma_kernel<<<NPIX / 128, 128, 99328>>>(x, bias, out);
    bn_relu_kernel<<<NELEM / 4 / 256, 256>>>((float4*)out, gamma, beta);
}

// round 11
// speedup vs baseline: 1.4041x; 1.4041x over previous
#include <cuda_runtime.h>
#include <cuda_fp16.h>
#include <math.h>
#include <stdint.h>

#define BB   8
#define CC   64
#define HH   128
#define WW   128
#define HWSZ (HH*WW)          // 16384
#define NPIX (BB*HWSZ)        // 131072
#define NELEM (BB*CC*HWSZ)    // 8388608
#define EPS  1e-5f

// scratch: offsets(18) + mask(9) per pixel, layout [b][27][h][w]
__device__ float g_om[BB * 27 * HWSZ];
// [0..63] = sum(y) per channel, [64..127] = sum(y^2)
__device__ float g_sums[128];
// deform weights: per tap, B tile [64 outch x 64 ch] fp16, SW128, 8KB/tap
__device__ uint4 g_wh[9 * 512];
// conv(offset+mask) weights: per tap, B tile [32 rows (27 used) x 64 ch], 4KB/tap
__device__ uint4 g_cwh[9 * 256];

#define SMEM_SWZ128(o) ((o) ^ (((o) >> 3) & 0x70))

__device__ __forceinline__ uint32_t smem_u32(const void* p) {
    uint32_t a;
    asm("{ .reg .u64 t; cvta.to.shared.u64 t, %1; cvt.u32.u64 %0, t; }" : "=r"(a) : "l"(p));
    return a;
}
__device__ __forceinline__ void ldm_x4(uint32_t* r, uint32_t addr) {
    asm volatile("ldmatrix.sync.aligned.m8n8.x4.shared.b16 {%0,%1,%2,%3}, [%4];"
        : "=r"(r[0]), "=r"(r[1]), "=r"(r[2]), "=r"(r[3]) : "r"(addr));
}
__device__ __forceinline__ void mma16816(float* d, const uint32_t* a, const uint32_t* b) {
    asm volatile("mma.sync.aligned.m16n8k16.row.col.f32.f16.f16.f32 "
        "{%0,%1,%2,%3}, {%4,%5,%6,%7}, {%8,%9}, {%0,%1,%2,%3};"
        : "+f"(d[0]), "+f"(d[1]), "+f"(d[2]), "+f"(d[3])
        : "r"(a[0]), "r"(a[1]), "r"(a[2]), "r"(a[3]), "r"(b[0]), "r"(b[1]));
}
// pack (a0 -> low half, a1 -> high half) as fp16x2
__device__ __forceinline__ uint32_t pack_h2(float a0, float a1) {
    uint32_t r;
    asm("cvt.rn.f16x2.f32 %0, %1, %2;" : "=r"(r) : "f"(a1), "f"(a0));
    return r;
}

// ---------------------------------------------------------------------------
// Kernel 0: repack all weights into fp16 pre-swizzled per-tap tiles.
// ids [0, 4608): deform w. ids [4608, 6912): offset/mask conv weights.
// ---------------------------------------------------------------------------
__global__ __launch_bounds__(128) void repack_w_kernel(
    const float* __restrict__ w,
    const float* __restrict__ off_w, const float* __restrict__ mod_w)
{
    int id = blockIdx.x * 128 + threadIdx.x;
    if (blockIdx.x == 0 && threadIdx.x < 128) g_sums[threadIdx.x] = 0.f;

    if (id < 9 * 64 * 8) {
        int k  = id / 512;
        int r  = id % 512;
        int o  = r / 8;
        int cg = r % 8;
        uint32_t hp[4];
#pragma unroll
        for (int jj = 0; jj < 4; ++jj) {
            int c0 = cg * 8 + 2 * jj;
            hp[jj] = pack_h2(w[o * 576 + (c0 + 0) * 9 + k],
                             w[o * 576 + (c0 + 1) * 9 + k]);
        }
        uint32_t off = SMEM_SWZ128((uint32_t)(o * 128 + cg * 16));
        g_wh[k * 512 + off / 16] = make_uint4(hp[0], hp[1], hp[2], hp[3]);
    } else if (id < 9 * 64 * 8 + 9 * 32 * 8) {
        int id2 = id - 9 * 64 * 8;
        int k  = id2 / 256;
        int r  = id2 % 256;
        int j  = r / 8;
        int cg = r % 8;
        uint32_t hp[4];
#pragma unroll
        for (int jj = 0; jj < 4; ++jj) {
            int c0 = cg * 8 + 2 * jj;
            float a0 = 0.f, a1 = 0.f;
            if (j < 18) {
                a0 = off_w[(j * 64 + c0 + 0) * 9 + k];
                a1 = off_w[(j * 64 + c0 + 1) * 9 + k];
            } else if (j < 27) {
                a0 = mod_w[((j - 18) * 64 + c0 + 0) * 9 + k];
                a1 = mod_w[((j - 18) * 64 + c0 + 1) * 9 + k];
            }
            hp[jj] = pack_h2(a0, a1);
        }
        uint32_t off = SMEM_SWZ128((uint32_t)(j * 128 + cg * 16));
        g_cwh[k * 256 + off / 16] = make_uint4(hp[0], hp[1], hp[2], hp[3]);
    }
}

// ---------------------------------------------------------------------------
// Kernel 1: offset/mask 3x3 conv via single-pass fp16 mma.sync.
// Block = 128 pixels, 4 warps. M=128, N=32 (27 used), K=64/tap.
// smem: A [128 x 128B] 16KB @ab, B [32 x 128B] 4KB @ab+16384.
// ---------------------------------------------------------------------------
__global__ __launch_bounds__(128) void conv_om_mma_kernel(
    const float* __restrict__ x,
    const float* __restrict__ off_b, const float* __restrict__ mod_b)
{
    extern __shared__ __align__(16) char dynsm[];
    uint32_t dynb = smem_u32(dynsm);
    uint32_t ab   = (dynb + 1023) & ~1023u;
    char* aptr    = dynsm + (ab - dynb);
    uint32_t sm_a = ab;
    uint32_t sm_b = ab + 16384;

    int tid  = threadIdx.x;
    int wid  = tid >> 5;
    int lane = tid & 31;

    int gid = blockIdx.x * 128 + tid;
    int b   = gid >> 14;
    int hw  = gid & (HWSZ - 1);
    int h   = hw >> 7;
    int wc  = hw & (WW - 1);
    const float* xb = x + b * CC * HWSZ;

    float acc[2][4][4];
#pragma unroll
    for (int m = 0; m < 2; ++m)
#pragma unroll
        for (int n = 0; n < 4; ++n)
#pragma unroll
            for (int q = 0; q < 4; ++q) acc[m][n][q] = 0.f;

    for (int k = 0; k < 9; ++k) {
        {
            const uint4* sh = g_cwh + k * 256;
            uint4* dh = (uint4*)(aptr + 16384);
            dh[tid] = sh[tid];
            dh[tid + 128] = sh[tid + 128];
        }

        int y  = h + k / 3 - 1;
        int xx = wc + k % 3 - 1;
        bool ok = (y >= 0) && (y < HH) && (xx >= 0) && (xx < WW);
        const float* xp = xb + y * WW + xx;
        uint32_t rowoff = (uint32_t)(tid * 128);
#pragma unroll
        for (int g8 = 0; g8 < 8; ++g8) {
            uint32_t hp[4];
#pragma unroll
            for (int jj = 0; jj < 4; ++jj) {
                int c0 = g8 * 8 + 2 * jj;
                float a0 = ok ? xp[(c0 + 0) * HWSZ] : 0.f;
                float a1 = ok ? xp[(c0 + 1) * HWSZ] : 0.f;
                hp[jj] = pack_h2(a0, a1);
            }
            uint32_t off = SMEM_SWZ128(rowoff + (uint32_t)(g8 * 16));
            *(uint4*)(aptr + off) = make_uint4(hp[0], hp[1], hp[2], hp[3]);
        }
        __syncthreads();

        int m0 = wid * 32;
        int brow = (lane & 7) + ((lane >> 4) << 3);
        int bcolh = ((lane >> 3) & 1) * 16;
        int arow = (lane & 15);
        int acolh = ((lane >> 4) & 1) * 16;
#pragma unroll
        for (int s = 0; s < 4; ++s) {
            uint32_t bh[4][2];
#pragma unroll
            for (int np = 0; np < 2; ++np) {
                uint32_t off = SMEM_SWZ128((uint32_t)((np * 16 + brow) * 128 + s * 32 + bcolh));
                uint32_t r[4];
                ldm_x4(r, sm_b + off);
                bh[np*2][0] = r[0]; bh[np*2][1] = r[1];
                bh[np*2+1][0] = r[2]; bh[np*2+1][1] = r[3];
            }
#pragma unroll
            for (int mt = 0; mt < 2; ++mt) {
                uint32_t off = SMEM_SWZ128((uint32_t)((m0 + mt * 16 + arow) * 128 + s * 32 + acolh));
                uint32_t ah[4];
                ldm_x4(ah, sm_a + off);
#pragma unroll
                for (int n = 0; n < 4; ++n)
                    mma16816(acc[mt][n], ah, bh[n]);
            }
        }
        __syncthreads();
    }

    // D[128][32] fp32 to smem (128B rows, XOR swizzle on 16B groups)
    {
        int m0 = wid * 32;
        int g  = lane >> 2;
        int t  = lane & 3;
#pragma unroll
        for (int mt = 0; mt < 2; ++mt) {
#pragma unroll
            for (int n = 0; n < 4; ++n) {
                int c0 = n * 8 + t * 2;
                int gq = c0 >> 2;
                int sub = (c0 & 3) * 4;
                int r0 = m0 + mt * 16 + g;
                int r1 = r0 + 8;
                uint32_t o0 = (uint32_t)(r0 * 128 + (((gq + r0) & 7) * 16) + sub);
                uint32_t o1 = (uint32_t)(r1 * 128 + (((gq + r1) & 7) * 16) + sub);
                *(float2*)(aptr + o0) = make_float2(acc[mt][n][0], acc[mt][n][1]);
                *(float2*)(aptr + o1) = make_float2(acc[mt][n][2], acc[mt][n][3]);
            }
        }
    }
    __syncthreads();

    float v[32];
#pragma unroll
    for (int g = 0; g < 8; ++g) {
        float4 q = *(float4*)(aptr + tid * 128 + (((g + tid) & 7) * 16));
        v[g * 4 + 0] = q.x; v[g * 4 + 1] = q.y;
        v[g * 4 + 2] = q.z; v[g * 4 + 3] = q.w;
    }
    float* om = g_om + b * 27 * HWSZ + hw;
#pragma unroll
    for (int j = 0; j < 18; ++j) om[j * HWSZ] = v[j] + __ldg(&off_b[j]);
#pragma unroll
    for (int j = 18; j < 27; ++j) {
        float a = v[j] + __ldg(&mod_b[j - 18]);
        om[j * HWSZ] = 2.f / (1.f + expf(-a));
    }
}

// ---------------------------------------------------------------------------
// Kernel 2: deformable gather -> single-pass fp16 mma.sync GEMM -> bias + BN.
// smem: A [128 x 128B] 16KB @ab, B [64 x 128B] 8KB @ab+16384;
// D staging 32KB reuses the whole region after the tap loop.
// ---------------------------------------------------------------------------
__global__ __launch_bounds__(128) void deform_mma_kernel(
    const float* __restrict__ x,
    const float* __restrict__ bias,
    float* __restrict__ out)
{
    extern __shared__ __align__(16) char dynsm[];
    uint32_t dynb = smem_u32(dynsm);
    uint32_t ab   = (dynb + 1023) & ~1023u;
    char* aptr    = dynsm + (ab - dynb);
    uint32_t sm_a = ab;
    uint32_t sm_b = ab + 16384;

    __shared__ float ssum[64];
    __shared__ float ssq[64];

    int tid  = threadIdx.x;
    int wid  = tid >> 5;
    int lane = tid & 31;

    if (tid < 64) { ssum[tid] = 0.f; ssq[tid] = 0.f; }

    int gid = blockIdx.x * 128 + tid;
    int b   = gid >> 14;
    int hw  = gid & (HWSZ - 1);
    int h   = hw >> 7;
    int wc  = hw & (WW - 1);
    const float* xb = x + b * CC * HWSZ;
    const float* om = g_om + b * 27 * HWSZ + hw;

    float acc[2][8][4];
#pragma unroll
    for (int m = 0; m < 2; ++m)
#pragma unroll
        for (int n = 0; n < 8; ++n)
#pragma unroll
            for (int q = 0; q < 4; ++q) acc[m][n][q] = 0.f;

    for (int k = 0; k < 9; ++k) {
        // stage B tile (8KB)
        {
            const uint4* sh = g_wh + k * 512;
            uint4* dh = (uint4*)(aptr + 16384);
#pragma unroll
            for (int i = 0; i < 4; ++i)
                dh[tid + 128 * i] = sh[tid + 128 * i];
        }

        float dy = om[(2 * k + 0) * HWSZ];
        float dx = om[(2 * k + 1) * HWSZ];
        float m  = om[(18 + k) * HWSZ];

        float py = (float)(h + k / 3 - 1) + dy;
        float px = (float)(wc + k % 3 - 1) + dx;
        float y0f = floorf(py), x0f = floorf(px);
        float ly = py - y0f, lx = px - x0f;
        int y0 = (int)y0f, x0 = (int)x0f;
        int y1 = y0 + 1, x1 = x0 + 1;

        bool vy0 = (y0 >= 0) && (y0 < HH);
        bool vy1 = (y1 >= 0) && (y1 < HH);
        bool vx0 = (x0 >= 0) && (x0 < WW);
        bool vx1 = (x1 >= 0) && (x1 < WW);
        int cy0 = min(max(y0, 0), HH - 1), cy1 = min(max(y1, 0), HH - 1);
        int cx0 = min(max(x0, 0), WW - 1), cx1 = min(max(x1, 0), WW - 1);
        int i00 = cy0 * WW + cx0, i01 = cy0 * WW + cx1;
        int i10 = cy1 * WW + cx0, i11 = cy1 * WW + cx1;

        float w00 = (vy0 && vx0) ? (1.f - ly) * (1.f - lx) * m : 0.f;
        float w01 = (vy0 && vx1) ? (1.f - ly) * lx * m : 0.f;
        float w10 = (vy1 && vx0) ? ly * (1.f - lx) * m : 0.f;
        float w11 = (vy1 && vx1) ? ly * lx * m : 0.f;

        uint32_t rowoff = (uint32_t)(tid * 128);
#pragma unroll
        for (int g8 = 0; g8 < 8; ++g8) {
            float v[8];
#pragma unroll
            for (int j = 0; j < 8; ++j) {
                const float* xc = xb + (g8 * 8 + j) * HWSZ;
                v[j] = w00 * xc[i00] + w01 * xc[i01] + w10 * xc[i10] + w11 * xc[i11];
            }
            uint32_t hp[4];
#pragma unroll
            for (int jj = 0; jj < 4; ++jj)
                hp[jj] = pack_h2(v[2 * jj], v[2 * jj + 1]);
            uint32_t off = SMEM_SWZ128(rowoff + (uint32_t)(g8 * 16));
            *(uint4*)(aptr + off) = make_uint4(hp[0], hp[1], hp[2], hp[3]);
        }
        __syncthreads();

        int m0 = wid * 32;
        int brow = (lane & 7) + ((lane >> 4) << 3);
        int bcolh = ((lane >> 3) & 1) * 16;
        int arow = (lane & 15);
        int acolh = ((lane >> 4) & 1) * 16;
#pragma unroll
        for (int s = 0; s < 4; ++s) {
            uint32_t bh[8][2];
#pragma unroll
            for (int np = 0; np < 4; ++np) {
                uint32_t off = SMEM_SWZ128((uint32_t)((np * 16 + brow) * 128 + s * 32 + bcolh));
                uint32_t r[4];
                ldm_x4(r, sm_b + off);
                bh[np*2][0] = r[0]; bh[np*2][1] = r[1];
                bh[np*2+1][0] = r[2]; bh[np*2+1][1] = r[3];
            }
#pragma unroll
            for (int mt = 0; mt < 2; ++mt) {
                uint32_t off = SMEM_SWZ128((uint32_t)((m0 + mt * 16 + arow) * 128 + s * 32 + acolh));
                uint32_t ah[4];
                ldm_x4(ah, sm_a + off);
#pragma unroll
                for (int n = 0; n < 8; ++n)
                    mma16816(acc[mt][n], ah, bh[n]);
            }
        }
        __syncthreads();
    }

    // write fragments to smem D[128][64] fp32 (XOR-swizzled 256B rows, 32KB)
    {
        int m0 = wid * 32;
        int g  = lane >> 2;
        int t  = lane & 3;
#pragma unroll
        for (int mt = 0; mt < 2; ++mt) {
#pragma unroll
            for (int n = 0; n < 8; ++n) {
                int col16 = n * 2 + (t >> 1);
                int lowb  = (t & 1) * 8;
                int r0 = m0 + mt * 16 + g;
                int r1 = r0 + 8;
                uint32_t o0 = (uint32_t)(r0 * 256 + (((col16 + r0) & 15) * 16) + lowb);
                uint32_t o1 = (uint32_t)(r1 * 256 + (((col16 + r1) & 15) * 16) + lowb);
                *(float2*)(aptr + o0) = make_float2(acc[mt][n][0], acc[mt][n][1]);
                *(float2*)(aptr + o1) = make_float2(acc[mt][n][2], acc[mt][n][3]);
            }
        }
    }
    __syncthreads();

    float v[64];
#pragma unroll
    for (int j = 0; j < 16; ++j) {
        float4 q = *(float4*)(aptr + tid * 256 + (((j + tid) & 15) * 16));
        v[j * 4 + 0] = q.x; v[j * 4 + 1] = q.y;
        v[j * 4 + 2] = q.z; v[j * 4 + 3] = q.w;
    }

    float* yp = out + b * CC * HWSZ + hw;
#pragma unroll
    for (int o = 0; o < 64; ++o) {
        float val = v[o] + __ldg(&bias[o]);
        yp[o * HWSZ] = val;
        float s = val, q = val * val;
#pragma unroll
        for (int d = 16; d > 0; d >>= 1) {
            s += __shfl_down_sync(0xffffffffu, s, d);
            q += __shfl_down_sync(0xffffffffu, q, d);
        }
        if (lane == 0) { atomicAdd(&ssum[o], s); atomicAdd(&ssq[o], q); }
    }
    __syncthreads();
    if (tid < 64) {
        atomicAdd(&g_sums[tid], ssum[tid]);
        atomicAdd(&g_sums[64 + tid], ssq[tid]);
    }
}

// ---------------------------------------------------------------------------
// Kernel 3: batchnorm + gamma/beta + relu, float4-vectorized, in place.
// ---------------------------------------------------------------------------
__global__ __launch_bounds__(256) void bn_relu_kernel(
    float4* __restrict__ out,
    const float* __restrict__ gamma, const float* __restrict__ beta)
{
    int gid = blockIdx.x * 256 + threadIdx.x;
    int c = (gid >> 12) & 63;
    const float N = (float)NPIX;
    float s = g_sums[c], q = g_sums[64 + c];
    float mean = s / N;
    float var = q / N - mean * mean;
    float inv = rsqrtf(var + EPS);
    float scale = __ldg(&gamma[c]) * inv;
    float shift = __ldg(&beta[c]) - mean * scale;
    float4 v = out[gid];
    v.x = fmaxf(v.x * scale + shift, 0.f);
    v.y = fmaxf(v.y * scale + shift, 0.f);
    v.z = fmaxf(v.z * scale + shift, 0.f);
    v.w = fmaxf(v.w * scale + shift, 0.f);
    out[gid] = v;
}

// ---------------------------------------------------------------------------
extern "C" void kernel_launch(void* const* d_in, const int* in_sizes, int n_in,
                              void* d_out, int out_size)
{
    const float* x     = (const float*)d_in[0];
    const float* off_w = (const float*)d_in[1];
    const float* off_b = (const float*)d_in[2];
    const float* mod_w = (const float*)d_in[3];
    const float* mod_b = (const float*)d_in[4];
    const float* w     = (const float*)d_in[5];
    const float* bias  = (const float*)d_in[6];
    const float* gamma = (const float*)d_in[7];
    const float* beta  = (const float*)d_in[8];
    float* out = (float*)d_out;

    static bool attr_set = false;
    if (!attr_set) {
        cudaFuncSetAttribute(deform_mma_kernel,
                             cudaFuncAttributeMaxDynamicSharedMemorySize, 33792);
        cudaFuncSetAttribute(conv_om_mma_kernel,
                             cudaFuncAttributeMaxDynamicSharedMemorySize, 21504);
        attr_set = true;
    }

    repack_w_kernel<<<54, 128>>>(w, off_w, mod_w);
    conv_om_mma_kernel<<<NPIX / 128, 128, 21504>>>(x, off_b, mod_b);
    deform_mma_kernel<<<NPIX / 128, 128, 33792>>>(x, bias, out);
    bn_relu_kernel<<<NELEM / 4 / 256, 256>>>((float4*)out, gamma, beta);
}